// round 7
// baseline (speedup 1.0000x reference)
#include <cuda_runtime.h>
#include <cuda_fp16.h>
#include <cstdint>

// ---------------- problem constants ----------------
#define NBODY     10
#define NPAIRS    90
#define HID       128
#define TILE      128
#define SELF_ROWS 81920
#define INT_ROWS  737280
#define SELF_TILES (SELF_ROWS / TILE)   // 640
#define INT_TILES  (INT_ROWS / TILE)    // 5760
#define NCTA      148
#define NTHREADS  512                   // 2 tile-streams of 256 threads
#define SH        144                   // half-stride per row (72 words; 72%32=8 -> conflict-free)

// smem byte offsets
#define OFF_W1T   0          // 128 x SH halfs                       36864 B
#define OFF_A     36864      // + stream*73728 + buf*36864  (2x2)   147456 B
#define OFF_INP   184320     // + stream*8192 + buf*4096             16384 B
#define OFF_P     200704     // + stream*8192                        16384 B
#define OFF_W0    217088     // 6*128 fp32 (zero-padded)              3072 B
#define OFF_B0    220160     // 128 fp32
#define OFF_B1    220672     // 128 fp32
#define OFF_W2    221184     // 128x4 fp32
#define OFF_B2    223232     // 4 fp32
#define SMEM_TOTAL 223248

__device__ float g_scratch[INT_ROWS * 4];

// ---------------- helpers ----------------
__device__ __forceinline__ float softplus_f(float x) {
    float e = __expf(-fabsf(x));
    return fmaxf(x, 0.0f) + __logf(1.0f + e);
}
// permute k within each 16-group so thread j's halfs (2j,2j+1,2j+8,2j+9) are contiguous
__device__ __forceinline__ int pos16h(int c) {
    return (c & ~15) | (((c >> 1) & 3) << 2) | (((c >> 3) & 1) << 1) | (c & 1);
}
__device__ __forceinline__ void mma_f16(float* c, uint32_t a0, uint32_t a1,
                                        uint32_t a2, uint32_t a3,
                                        uint32_t b0, uint32_t b1) {
    asm("mma.sync.aligned.m16n8k16.row.col.f32.f16.f16.f32 "
        "{%0,%1,%2,%3}, {%4,%5,%6,%7}, {%8,%9}, {%0,%1,%2,%3};"
        : "+f"(c[0]), "+f"(c[1]), "+f"(c[2]), "+f"(c[3])
        : "r"(a0), "r"(a1), "r"(a2), "r"(a3), "r"(b0), "r"(b1));
}

__device__ __forceinline__ void build_row(float* dst, const float4* z4, int grow, bool isSelf) {
    if (isSelf) {
        *(float4*)dst       = z4[grow];
        *(float4*)(dst + 4) = make_float4(0.f, 0.f, 0.f, 0.f);
    } else {
        int n   = grow / NPAIRS;
        int pr  = grow - n * NPAIRS;
        int rec = pr / (NBODY - 1);
        int sr  = pr - rec * (NBODY - 1);
        int snd = sr + (sr >= rec ? 1 : 0);
        float4 zr = z4[n * NBODY + rec];
        float4 zs = z4[n * NBODY + snd];
        *(float4*)dst       = make_float4(zr.x - zs.x, zr.y - zs.y, zr.z, zr.w);
        *(float4*)(dst + 4) = make_float4(zs.z, zs.w, 0.0f, 0.0f);
    }
}

// ---------------- two-phase persistent fused MLP ----------------
__global__ __launch_bounds__(NTHREADS, 1)
void mlp_all(const float* __restrict__ z,
             const float* __restrict__ fW0, const float* __restrict__ fb0,
             const float* __restrict__ fW1, const float* __restrict__ fb1,
             const float* __restrict__ fW2, const float* __restrict__ fb2,
             const float* __restrict__ iW0, const float* __restrict__ ib0,
             const float* __restrict__ iW1, const float* __restrict__ ib1,
             const float* __restrict__ iW2, const float* __restrict__ ib2,
             float* __restrict__ out_self)
{
    extern __shared__ __align__(16) char smem[];
    __half* W1h = (__half*)(smem + OFF_W1T);
    float*  W0s = (float*)(smem + OFF_W0);
    float*  b0s = (float*)(smem + OFF_B0);
    float*  b1s = (float*)(smem + OFF_B1);
    const float4* W2v = (const float4*)(smem + OFF_W2);
    float*  b2s = (float*)(smem + OFF_B2);

    const int tid  = threadIdx.x;
    const int wg   = tid >> 8;            // tile stream 0/1
    const int wt   = tid & 255;
    const int w8   = wt >> 5;             // warp in stream: 0..7
    const int lane = tid & 31;
    const int g    = lane >> 2;
    const int j    = lane & 3;
    const int mi   = w8 >> 2;             // rows mi*64..+63
    const int ni   = w8 & 3;              // cols ni*32..+31

    __half* AhS  = (__half*)(smem + OFF_A + wg * 73728);       // + buf*36864B
    float*  inpS = (float*)(smem + OFF_INP + wg * 8192);       // + buf*1024 floats
    float*  P    = (float*)(smem + OFF_P + wg * 8192);
    const int wbar = 1 + wg;
    const float4* z4 = (const float4*)z;

    // layer0 thread mapping (thread = column col, row-half wt>>7)
    const int col   = wt & 127;
    const int rbase = (wt >> 7) * 64;
    const int pc    = pos16h(col);
    const int r0 = mi * 64, n0 = ni * 32;
    const int nstride = gridDim.x * 2;

    #pragma unroll 1
    for (int phase = 0; phase < 2; phase++) {
        const bool isSelf = (phase == 1);
        const float* W0 = isSelf ? fW0 : iW0;
        const float* b0 = isSelf ? fb0 : ib0;
        const float* W1 = isSelf ? fW1 : iW1;
        const float* b1 = isSelf ? fb1 : ib1;
        const float* W2 = isSelf ? fW2 : iW2;
        const float* b2 = isSelf ? fb2 : ib2;
        float* out = isSelf ? out_self : g_scratch;
        const int ntiles = isSelf ? SELF_TILES : INT_TILES;
        const int NIN = isSelf ? 4 : 6;

        // ---- stage weights for this phase ----
        for (int i = tid; i < HID * HID; i += NTHREADS) {
            int k = i >> 7, n = i & 127;
            W1h[n * SH + pos16h(k)] = __float2half_rn(W1[i]);   // B as [n][pos(k)]
        }
        for (int i = tid; i < 6 * HID; i += NTHREADS)
            W0s[i] = (i < NIN * HID) ? W0[i] : 0.0f;
        if (tid < HID) { b0s[tid] = b0[tid]; b1s[tid] = b1[tid]; }
        for (int i = tid; i < HID * 4; i += NTHREADS)
            ((float*)(smem + OFF_W2))[i] = W2[i];
        if (tid < 4) b2s[tid] = b2[tid];
        __syncthreads();

        const float4 b2v = *(const float4*)b2s;
        float w0r[6];
        #pragma unroll
        for (int q = 0; q < 6; q++) w0r[q] = W0s[q * HID + col];
        const float b0c = b0s[col];

        // ---- prologue: build inputs for first tile into buffer 0 ----
        const int t0 = blockIdx.x * 2 + wg;
        if (wt < 128 && t0 < ntiles)
            build_row(inpS + wt * 8, z4, t0 * TILE + wt, isSelf);
        asm volatile("bar.sync %0, 256;" :: "r"(wbar) : "memory");

        int buf = 0;
        for (int t = t0; t < ntiles; t += nstride) {
            const int rowBase = t * TILE;
            const float*  inp = inpS + buf * 1024;
            __half* Ah = (__half*)((char*)AhS + buf * 36864);

            // ---- layer 0: Ah[r][pos(col)] = h(softplus(inp[r].W0[:,col]+b0)) ----
            #pragma unroll 4
            for (int r = 0; r < 64; r++) {
                float4 i0 = *(const float4*)&inp[(rbase + r) * 8];
                float4 i1 = *(const float4*)&inp[(rbase + r) * 8 + 4];
                float a = b0c;
                a = fmaf(i0.x, w0r[0], a); a = fmaf(i0.y, w0r[1], a);
                a = fmaf(i0.z, w0r[2], a); a = fmaf(i0.w, w0r[3], a);
                a = fmaf(i1.x, w0r[4], a); a = fmaf(i1.y, w0r[5], a);
                Ah[(rbase + r) * SH + pc] = __float2half_rn(softplus_f(a));
            }

            // ---- build inputs for next tile into other buffer ----
            {
                int tn = t + nstride;
                if (wt < 128 && tn < ntiles)
                    build_row(inpS + (buf ^ 1) * 1024 + wt * 8, z4, tn * TILE + wt, isSelf);
            }
            asm volatile("bar.sync %0, 256;" :: "r"(wbar) : "memory");

            // ---- layer 1: 64x32 warp tile, m16n8k16 fp16, 8 k-steps ----
            float c[4][4][4];
            #pragma unroll
            for (int mt = 0; mt < 4; mt++)
                #pragma unroll
                for (int nt = 0; nt < 4; nt++)
                    #pragma unroll
                    for (int q = 0; q < 4; q++) c[mt][nt][q] = 0.0f;

            #pragma unroll 1
            for (int s = 0; s < 8; s++) {
                const int koff = s * 16 + 4 * j;
                uint2 bf[4], lo[4], hi[4];
                #pragma unroll
                for (int nt = 0; nt < 4; nt++)
                    bf[nt] = *(const uint2*)&W1h[(n0 + nt * 8 + g) * SH + koff];
                #pragma unroll
                for (int mt = 0; mt < 4; mt++) {
                    lo[mt] = *(const uint2*)&Ah[(r0 + mt * 16 + g) * SH + koff];
                    hi[mt] = *(const uint2*)&Ah[(r0 + mt * 16 + 8 + g) * SH + koff];
                }
                #pragma unroll
                for (int mt = 0; mt < 4; mt++)
                    #pragma unroll
                    for (int nt = 0; nt < 4; nt++)
                        mma_f16(c[mt][nt], lo[mt].x, hi[mt].x, lo[mt].y, hi[mt].y,
                                bf[nt].x, bf[nt].y);
            }

            // ---- epilogue: h1 = softplus(D + b1); partial = h1 @ W2 ----
            float  b1r[8];
            float4 w2r[8];
            #pragma unroll
            for (int nt = 0; nt < 4; nt++)
                #pragma unroll
                for (int kk = 0; kk < 2; kk++) {
                    int cc = n0 + nt * 8 + 2 * j + kk;
                    b1r[nt * 2 + kk] = b1s[cc];
                    w2r[nt * 2 + kk] = W2v[cc];
                }
            #pragma unroll
            for (int mt = 0; mt < 4; mt++) {
                #pragma unroll
                for (int rr = 0; rr < 2; rr++) {
                    float4 p = make_float4(0.f, 0.f, 0.f, 0.f);
                    #pragma unroll
                    for (int nt = 0; nt < 4; nt++)
                        #pragma unroll
                        for (int kk = 0; kk < 2; kk++) {
                            float h = softplus_f(c[mt][nt][rr * 2 + kk] + b1r[nt * 2 + kk]);
                            float4 wv = w2r[nt * 2 + kk];
                            p.x = fmaf(h, wv.x, p.x); p.y = fmaf(h, wv.y, p.y);
                            p.z = fmaf(h, wv.z, p.z); p.w = fmaf(h, wv.w, p.w);
                        }
                    #pragma unroll
                    for (int msk = 1; msk <= 2; msk <<= 1) {
                        p.x += __shfl_xor_sync(0xffffffffu, p.x, msk);
                        p.y += __shfl_xor_sync(0xffffffffu, p.y, msk);
                        p.z += __shfl_xor_sync(0xffffffffu, p.z, msk);
                        p.w += __shfl_xor_sync(0xffffffffu, p.w, msk);
                    }
                    if (j == 0) {
                        int row = r0 + mt * 16 + rr * 8 + g;
                        *(float4*)&P[(ni * 128 + row) * 4] = p;
                    }
                }
            }
            asm volatile("bar.sync %0, 256;" :: "r"(wbar) : "memory");

            if (wt < 128) {
                const float4* P4 = (const float4*)P;
                float4 o4 = b2v;
                #pragma unroll
                for (int q = 0; q < 4; q++) {
                    float4 v = P4[q * 128 + wt];
                    o4.x += v.x; o4.y += v.y; o4.z += v.z; o4.w += v.w;
                }
                ((float4*)out)[rowBase + wt] = o4;
            }
            buf ^= 1;
        }
        __syncthreads();   // both streams done before restaging weights
    }
}

// out[n,rec,:] += sum_{j} scratch[n*90 + rec*9 + j, :]
__global__ void reduce_kernel(float* __restrict__ out)
{
    int r = blockIdx.x * blockDim.x + threadIdx.x;
    if (r >= SELF_ROWS) return;
    int n = r / NBODY, rec = r - n * NBODY;
    const float4* sc = (const float4*)g_scratch;
    int base = n * NPAIRS + rec * (NBODY - 1);
    float4 s = sc[base];
    #pragma unroll
    for (int q = 1; q < NBODY - 1; q++) {
        float4 v = sc[base + q];
        s.x += v.x; s.y += v.y; s.z += v.z; s.w += v.w;
    }
    float4 o = ((float4*)out)[r];
    o.x += s.x; o.y += s.y; o.z += s.z; o.w += s.w;
    ((float4*)out)[r] = o;
}

extern "C" void kernel_launch(void* const* d_in, const int* in_sizes, int n_in,
                              void* d_out, int out_size)
{
    const float* z   = (const float*)d_in[0];
    const float* fW0 = (const float*)d_in[1];
    const float* fb0 = (const float*)d_in[2];
    const float* fW1 = (const float*)d_in[3];
    const float* fb1 = (const float*)d_in[4];
    const float* fW2 = (const float*)d_in[5];
    const float* fb2 = (const float*)d_in[6];
    const float* iW0 = (const float*)d_in[7];
    const float* ib0 = (const float*)d_in[8];
    const float* iW1 = (const float*)d_in[9];
    const float* ib1 = (const float*)d_in[10];
    const float* iW2 = (const float*)d_in[11];
    const float* ib2 = (const float*)d_in[12];
    float* out = (float*)d_out;

    cudaFuncSetAttribute(mlp_all, cudaFuncAttributeMaxDynamicSharedMemorySize, SMEM_TOTAL);

    mlp_all<<<NCTA, NTHREADS, SMEM_TOTAL>>>(z, fW0, fb0, fW1, fb1, fW2, fb2,
                                            iW0, ib0, iW1, ib1, iW2, ib2, out);
    reduce_kernel<<<(SELF_ROWS + 255) / 256, 256>>>(out);
}

// round 8
// speedup vs baseline: 1.9430x; 1.9430x over previous
#include <cuda_runtime.h>
#include <cuda_fp16.h>
#include <cstdint>

// ---------------- problem constants ----------------
#define NBODY     10
#define NPAIRS    90
#define HID       128
#define TILE      128
#define SELF_ROWS 81920
#define INT_ROWS  737280
#define SELF_TILES (SELF_ROWS / TILE)   // 640
#define INT_TILES  (INT_ROWS / TILE)    // 5760
#define NCTA      148
#define NTHREADS  512                   // 2 tile-streams of 256 threads
#define SW        72                    // row stride in 32-bit words (72%32=8, conflict-free)

// smem byte offsets
#define OFF_W1T   0          // 128 x SW half2-words                 36864 B
#define OFF_A0    36864      // stream 0 H0: 128 x SW half2-words    36864 B
#define OFF_A1    73728      // stream 1                             36864 B
#define OFF_P0    110592     // stream 0: inp overlay (4KB) / partials 8KB
#define OFF_P1    118784
#define OFF_W0    126976     // 6*128 fp32 (zero-padded)
#define OFF_B0    130048     // 128 fp32
#define OFF_B1    130560     // 128 fp32
#define OFF_W2    131072     // 128x4 fp32
#define OFF_B2    133120     // 4 fp32
#define SMEM_TOTAL 133136

__device__ float g_scratch[INT_ROWS * 4];

// ---------------- helpers ----------------
__device__ __forceinline__ float softplus_f(float x) {
    float e = __expf(-fabsf(x));
    return fmaxf(x, 0.0f) + __logf(1.0f + e);
}
// permute words within each 8-group so (u, u+4) are adjacent -> uint2 loads
__device__ __forceinline__ int pos8(int c) {
    return (c & ~7) | ((c & 3) << 1) | ((c >> 2) & 1);
}
__device__ __forceinline__ void mma_f16(float* c, uint32_t a0, uint32_t a1,
                                        uint32_t a2, uint32_t a3,
                                        uint32_t b0, uint32_t b1) {
    asm("mma.sync.aligned.m16n8k16.row.col.f32.f16.f16.f32 "
        "{%0,%1,%2,%3}, {%4,%5,%6,%7}, {%8,%9}, {%0,%1,%2,%3};"
        : "+f"(c[0]), "+f"(c[1]), "+f"(c[2]), "+f"(c[3])
        : "r"(a0), "r"(a1), "r"(a2), "r"(a3), "r"(b0), "r"(b1));
}

// ---------------- two-phase persistent fused MLP ----------------
__global__ __launch_bounds__(NTHREADS, 1)
void mlp_all(const float* __restrict__ z,
             const float* __restrict__ fW0, const float* __restrict__ fb0,
             const float* __restrict__ fW1, const float* __restrict__ fb1,
             const float* __restrict__ fW2, const float* __restrict__ fb2,
             const float* __restrict__ iW0, const float* __restrict__ ib0,
             const float* __restrict__ iW1, const float* __restrict__ ib1,
             const float* __restrict__ iW2, const float* __restrict__ ib2,
             float* __restrict__ out_self)
{
    extern __shared__ __align__(16) char smem[];
    uint32_t* W1w = (uint32_t*)(smem + OFF_W1T);   // half2 words
    float*  W0s = (float*)(smem + OFF_W0);
    float*  b0s = (float*)(smem + OFF_B0);
    float*  b1s = (float*)(smem + OFF_B1);
    const float4* W2v = (const float4*)(smem + OFF_W2);
    float*  b2s = (float*)(smem + OFF_B2);

    const int tid  = threadIdx.x;
    const int wg   = tid >> 8;            // tile stream 0/1
    const int wt   = tid & 255;
    const int w8   = wt >> 5;             // warp in stream: 0..7
    const int lane = tid & 31;
    const int g    = lane >> 2;
    const int j    = lane & 3;
    const int mi   = w8 >> 2;             // rows mi*64..+63
    const int ni   = w8 & 3;              // cols ni*32..+31

    uint32_t* Aw  = (uint32_t*)(smem + OFF_A0 + wg * 36864);   // half2 words
    float*    P   = (float*)(smem + OFF_P0 + wg * 8192);
    float*    inp = P;                    // overlay: dead before partials written
    const int wbar = 1 + wg;

    // layer0 thread mapping: word-column u (= col pair 2u,2u+1), 32-row quarter
    const int u     = wt & 63;
    const int rq    = wt >> 6;            // 0..3
    const int pu    = pos8(u);
    const int r0 = mi * 64, n0 = ni * 32;

    #pragma unroll 1
    for (int phase = 0; phase < 2; phase++) {
        const bool isSelf = (phase == 1);
        const float* W0 = isSelf ? fW0 : iW0;
        const float* b0 = isSelf ? fb0 : ib0;
        const float* W1 = isSelf ? fW1 : iW1;
        const float* b1 = isSelf ? fb1 : ib1;
        const float* W2 = isSelf ? fW2 : iW2;
        const float* b2 = isSelf ? fb2 : ib2;
        float* out = isSelf ? out_self : g_scratch;
        const int ntiles = isSelf ? SELF_TILES : INT_TILES;
        const int NIN = isSelf ? 4 : 6;

        // ---- stage weights for this phase ----
        // B word: row n, word uu -> halfs (W1[2uu][n], W1[2uu+1][n])
        for (int i = tid; i < 64 * HID; i += NTHREADS) {
            int uu = i >> 7, n = i & 127;
            __half2 v = __floats2half2_rn(W1[(2 * uu) * HID + n],
                                          (2 * uu + 1) * HID + n < HID * HID
                                              ? W1[(2 * uu + 1) * HID + n] : 0.0f);
            W1w[n * SW + pos8(uu)] = *(uint32_t*)&v;
        }
        for (int i = tid; i < 6 * HID; i += NTHREADS)
            W0s[i] = (i < NIN * HID) ? W0[i] : 0.0f;
        if (tid < HID) { b0s[tid] = b0[tid]; b1s[tid] = b1[tid]; }
        for (int i = tid; i < HID * 4; i += NTHREADS)
            ((float*)(smem + OFF_W2))[i] = W2[i];
        if (tid < 4) b2s[tid] = b2[tid];
        __syncthreads();

        const float4 b2v = *(const float4*)b2s;
        float w0a[6], w0b[6];
        #pragma unroll
        for (int q = 0; q < 6; q++) {
            w0a[q] = W0s[q * HID + 2 * u];
            w0b[q] = W0s[q * HID + 2 * u + 1];
        }
        const float b0a = b0s[2 * u], b0b = b0s[2 * u + 1];

        for (int t = blockIdx.x * 2 + wg; t < ntiles; t += gridDim.x * 2) {
            const int rowBase = t * TILE;

            // ---- build 128 input rows ----
            if (wt < 128) {
                int grow = rowBase + wt;
                if (isSelf) {
                    float4 zz = ((const float4*)z)[grow];
                    *(float4*)&inp[wt * 8]     = zz;
                    *(float4*)&inp[wt * 8 + 4] = make_float4(0.f, 0.f, 0.f, 0.f);
                } else {
                    int n   = grow / NPAIRS;
                    int pr  = grow - n * NPAIRS;
                    int rec = pr / (NBODY - 1);
                    int sr  = pr - rec * (NBODY - 1);
                    int snd = sr + (sr >= rec ? 1 : 0);
                    float4 zr = ((const float4*)z)[n * NBODY + rec];
                    float4 zs = ((const float4*)z)[n * NBODY + snd];
                    *(float4*)&inp[wt * 8]     = make_float4(zr.x - zs.x, zr.y - zs.y, zr.z, zr.w);
                    *(float4*)&inp[wt * 8 + 4] = make_float4(zs.z, zs.w, 0.0f, 0.0f);
                }
            }
            asm volatile("bar.sync %0, 256;" :: "r"(wbar) : "memory");

            // ---- layer 0: cols (2u,2u+1) for 32 rows, one half2 STS.32 each ----
            #pragma unroll 4
            for (int r = 0; r < 32; r++) {
                const int row = rq * 32 + r;
                float4 i0 = *(const float4*)&inp[row * 8];
                float4 i1 = *(const float4*)&inp[row * 8 + 4];
                float a = b0a, b = b0b;
                a = fmaf(i0.x, w0a[0], a);  b = fmaf(i0.x, w0b[0], b);
                a = fmaf(i0.y, w0a[1], a);  b = fmaf(i0.y, w0b[1], b);
                a = fmaf(i0.z, w0a[2], a);  b = fmaf(i0.z, w0b[2], b);
                a = fmaf(i0.w, w0a[3], a);  b = fmaf(i0.w, w0b[3], b);
                a = fmaf(i1.x, w0a[4], a);  b = fmaf(i1.x, w0b[4], b);
                a = fmaf(i1.y, w0a[5], a);  b = fmaf(i1.y, w0b[5], b);
                __half2 hv = __floats2half2_rn(softplus_f(a), softplus_f(b));
                Aw[row * SW + pu] = *(uint32_t*)&hv;
            }
            asm volatile("bar.sync %0, 256;" :: "r"(wbar) : "memory");

            // ---- layer 1: 64x32 warp tile, m16n8k16 fp16, 8 k-steps ----
            float c[4][4][4];
            #pragma unroll
            for (int mt = 0; mt < 4; mt++)
                #pragma unroll
                for (int nt = 0; nt < 4; nt++)
                    #pragma unroll
                    for (int q = 0; q < 4; q++) c[mt][nt][q] = 0.0f;

            #pragma unroll 1
            for (int s = 0; s < 8; s++) {
                const int kw = s * 8 + 2 * j;      // word offset within row
                uint2 bf[4], lo[4], hi[4];
                #pragma unroll
                for (int nt = 0; nt < 4; nt++)
                    bf[nt] = *(const uint2*)&W1w[(n0 + nt * 8 + g) * SW + kw];
                #pragma unroll
                for (int mt = 0; mt < 4; mt++) {
                    lo[mt] = *(const uint2*)&Aw[(r0 + mt * 16 + g) * SW + kw];
                    hi[mt] = *(const uint2*)&Aw[(r0 + mt * 16 + 8 + g) * SW + kw];
                }
                #pragma unroll
                for (int mt = 0; mt < 4; mt++)
                    #pragma unroll
                    for (int nt = 0; nt < 4; nt++)
                        mma_f16(c[mt][nt], lo[mt].x, hi[mt].x, lo[mt].y, hi[mt].y,
                                bf[nt].x, bf[nt].y);
            }

            // ---- epilogue: h1 = softplus(D + b1); partial = h1 @ W2 ----
            float  b1r[8];
            float4 w2r[8];
            #pragma unroll
            for (int nt = 0; nt < 4; nt++)
                #pragma unroll
                for (int kk = 0; kk < 2; kk++) {
                    int cc = n0 + nt * 8 + 2 * j + kk;
                    b1r[nt * 2 + kk] = b1s[cc];
                    w2r[nt * 2 + kk] = W2v[cc];
                }
            #pragma unroll
            for (int mt = 0; mt < 4; mt++) {
                #pragma unroll
                for (int rr = 0; rr < 2; rr++) {
                    float4 p = make_float4(0.f, 0.f, 0.f, 0.f);
                    #pragma unroll
                    for (int nt = 0; nt < 4; nt++)
                        #pragma unroll
                        for (int kk = 0; kk < 2; kk++) {
                            float h = softplus_f(c[mt][nt][rr * 2 + kk] + b1r[nt * 2 + kk]);
                            float4 wv = w2r[nt * 2 + kk];
                            p.x = fmaf(h, wv.x, p.x); p.y = fmaf(h, wv.y, p.y);
                            p.z = fmaf(h, wv.z, p.z); p.w = fmaf(h, wv.w, p.w);
                        }
                    #pragma unroll
                    for (int msk = 1; msk <= 2; msk <<= 1) {
                        p.x += __shfl_xor_sync(0xffffffffu, p.x, msk);
                        p.y += __shfl_xor_sync(0xffffffffu, p.y, msk);
                        p.z += __shfl_xor_sync(0xffffffffu, p.z, msk);
                        p.w += __shfl_xor_sync(0xffffffffu, p.w, msk);
                    }
                    if (j == 0) {
                        int row = r0 + mt * 16 + rr * 8 + g;
                        *(float4*)&P[(ni * 128 + row) * 4] = p;
                    }
                }
            }
            asm volatile("bar.sync %0, 256;" :: "r"(wbar) : "memory");

            if (wt < 128) {
                const float4* P4 = (const float4*)P;
                float4 o4 = b2v;
                #pragma unroll
                for (int q = 0; q < 4; q++) {
                    float4 v = P4[q * 128 + wt];
                    o4.x += v.x; o4.y += v.y; o4.z += v.z; o4.w += v.w;
                }
                ((float4*)out)[rowBase + wt] = o4;
            }
            asm volatile("bar.sync %0, 256;" :: "r"(wbar) : "memory");
        }
        __syncthreads();   // both streams done before restaging weights
    }
}

// out[n,rec,:] += sum_{j} scratch[n*90 + rec*9 + j, :]
__global__ void reduce_kernel(float* __restrict__ out)
{
    int r = blockIdx.x * blockDim.x + threadIdx.x;
    if (r >= SELF_ROWS) return;
    int n = r / NBODY, rec = r - n * NBODY;
    const float4* sc = (const float4*)g_scratch;
    int base = n * NPAIRS + rec * (NBODY - 1);
    float4 s = sc[base];
    #pragma unroll
    for (int q = 1; q < NBODY - 1; q++) {
        float4 v = sc[base + q];
        s.x += v.x; s.y += v.y; s.z += v.z; s.w += v.w;
    }
    float4 o = ((float4*)out)[r];
    o.x += s.x; o.y += s.y; o.z += s.z; o.w += s.w;
    ((float4*)out)[r] = o;
}

extern "C" void kernel_launch(void* const* d_in, const int* in_sizes, int n_in,
                              void* d_out, int out_size)
{
    const float* z   = (const float*)d_in[0];
    const float* fW0 = (const float*)d_in[1];
    const float* fb0 = (const float*)d_in[2];
    const float* fW1 = (const float*)d_in[3];
    const float* fb1 = (const float*)d_in[4];
    const float* fW2 = (const float*)d_in[5];
    const float* fb2 = (const float*)d_in[6];
    const float* iW0 = (const float*)d_in[7];
    const float* ib0 = (const float*)d_in[8];
    const float* iW1 = (const float*)d_in[9];
    const float* ib1 = (const float*)d_in[10];
    const float* iW2 = (const float*)d_in[11];
    const float* ib2 = (const float*)d_in[12];
    float* out = (float*)d_out;

    cudaFuncSetAttribute(mlp_all, cudaFuncAttributeMaxDynamicSharedMemorySize, SMEM_TOTAL);

    mlp_all<<<NCTA, NTHREADS, SMEM_TOTAL>>>(z, fW0, fb0, fW1, fb1, fW2, fb2,
                                            iW0, ib0, iW1, ib1, iW2, ib2, out);
    reduce_kernel<<<(SELF_ROWS + 255) / 256, 256>>>(out);
}